// round 10
// baseline (speedup 1.0000x reference)
#include <cuda_runtime.h>
#include <cuda_fp16.h>
#include <math.h>
#include <stdint.h>

#define H_DIM 1024
#define FFN_DIM 4096
#define B_ROWS 4096
#define D_IN 784
#define K_EMB 800
#define D_OUT 1000
#define N_STEPS 30
#define LN_EPS 1e-5f

// ---------------- scratch (device globals; no allocation allowed) ----------
__device__ float  g_h[(size_t)B_ROWS * H_DIM];        // 16 MB fp32 state
__device__ float  g_xemb[(size_t)B_ROWS * H_DIM];     // 16 MB fp32
__device__ __half g_hn[(size_t)B_ROWS * H_DIM];       // 8 MB  (LN out / head A)
__device__ __half g_ffn[(size_t)B_ROWS * FFN_DIM];    // 32 MB (tanh out)
__device__ __half g_w1h[(size_t)FFN_DIM * H_DIM];     // 8 MB
__device__ __half g_w2h[(size_t)H_DIM * FFN_DIM];     // 8 MB
__device__ __half g_xh [(size_t)B_ROWS * K_EMB];      // 6.5 MB (x padded)
__device__ __half g_ewh[(size_t)H_DIM * K_EMB];       // 1.6 MB (embed_w padded)
__device__ __half g_hwh[(size_t)D_OUT * H_DIM];       // 2 MB   (head_w)

// ---------------- PTX helpers ----------------------------------------------
__device__ __forceinline__ uint32_t smem_u32(const void* p) {
    return (uint32_t)__cvta_generic_to_shared(p);
}
__device__ __forceinline__ void cp16(uint32_t dst, const void* src, int sz) {
    asm volatile("cp.async.cg.shared.global [%0], [%1], 16, %2;"
                 :: "r"(dst), "l"(src), "r"(sz));
}
__device__ __forceinline__ void cp_commit() { asm volatile("cp.async.commit_group;"); }
__device__ __forceinline__ void cp_wait1() {
    asm volatile("cp.async.wait_group 1;" ::: "memory");
}
__device__ __forceinline__ void ldsm_x4(uint32_t addr, uint32_t& r0, uint32_t& r1,
                                        uint32_t& r2, uint32_t& r3) {
    asm volatile("ldmatrix.sync.aligned.m8n8.x4.shared.b16 {%0,%1,%2,%3}, [%4];"
                 : "=r"(r0), "=r"(r1), "=r"(r2), "=r"(r3) : "r"(addr));
}
__device__ __forceinline__ void mma_f16(float* d, const uint32_t* a, uint32_t b0, uint32_t b1) {
    asm volatile("mma.sync.aligned.m16n8k16.row.col.f32.f16.f16.f32 "
                 "{%0,%1,%2,%3}, {%4,%5,%6,%7}, {%8,%9}, {%0,%1,%2,%3};"
                 : "+f"(d[0]), "+f"(d[1]), "+f"(d[2]), "+f"(d[3])
                 : "r"(a[0]), "r"(a[1]), "r"(a[2]), "r"(a[3]), "r"(b0), "r"(b1));
}

// ---------------------------------------------------------------------------
// FP16 tensor GEMM: C[M,N] = epi( A[M,K] @ W[N,K]^T + bias[N] )
// CTA tile 128x256, BK=32, 3-stage cp.async ring, 256 threads (8 warps, 2x4),
// warp tile 64x64, m16n8k16 f16 mma, fp32 accumulators.
// M%128==0, K%32==0; N guarded (zfill with clamped src addr + epilogue guard).
// MODE 0: C(fp32)=v, C2(fp32)=v if set
// MODE 1: C(fp16)=half(tanh(v))
// MODE 2: C(fp32)=0.5*Hold + 0.5*(v + Xemb)
// ---------------------------------------------------------------------------
#define ST 40                              // smem row stride in halves
#define TILE_A_BYTES (128 * ST * 2)        // 10240
#define TILE_B_BYTES (256 * ST * 2)        // 20480
#define STAGE_BYTES (TILE_A_BYTES + TILE_B_BYTES)  // 30720
#define SMEM_BYTES (3 * STAGE_BYTES)       // 92160

template <int MODE>
__global__ __launch_bounds__(256, 1)
void f16_gemm(const __half* __restrict__ A, const __half* __restrict__ W,
              const float* __restrict__ bias, void* __restrict__ Cv,
              float* __restrict__ C2, const float* __restrict__ Hold,
              const float* __restrict__ Xemb, int M, int N, int K)
{
    extern __shared__ char smem[];
    const uint32_t sb = smem_u32(smem);
    const int tid  = threadIdx.x;
    const int lane = tid & 31;
    const int warp = tid >> 5;
    const int wm = warp >> 2;              // 0..1 (64-row bands)
    const int wn = warp & 3;               // 0..3 (64-col bands)
    const int bm = blockIdx.y * 128;
    const int bn = blockIdx.x * 256;
    const int nst = K >> 5;

    // ldmatrix per-thread byte offsets within a stage
    const int grp = lane >> 3, r8 = lane & 7;
    const uint32_t aoff = (uint32_t)(((wm * 64 + (lane & 15)) * ST + (lane >> 4) * 8) * 2);
    const uint32_t boff = (uint32_t)TILE_A_BYTES +
        (uint32_t)(((wn * 64 + (grp >> 1) * 8 + r8) * ST + (grp & 1) * 8) * 2);

    float acc[4][8][4];
    #pragma unroll
    for (int i = 0; i < 4; i++)
        #pragma unroll
        for (int j = 0; j < 8; j++)
            #pragma unroll
            for (int r = 0; r < 4; r++) acc[i][j][r] = 0.0f;

    auto load_stage = [&](int s) {
        if (s >= nst) return;
        const uint32_t stb = sb + (uint32_t)(s % 3) * STAGE_BYTES;
        const int k0 = s << 5;
        #pragma unroll
        for (int i = 0; i < 6; i++) {
            const int c = tid + (i << 8);   // 0..1535
            if (c < 512) {                  // A: 128 rows x 4 x 16B
                const int row = c >> 2, kc = c & 3;
                cp16(stb + (uint32_t)((row * ST + kc * 8) * 2),
                     A + (size_t)(bm + row) * K + k0 + kc * 8, 16);
            } else {                        // W: 256 rows x 4 x 16B (zfill > N)
                const int c2 = c - 512;
                const int row = c2 >> 2, kc = c2 & 3;
                const int ok = ((bn + row) < N) ? 16 : 0;
                const int wr = ((bn + row) < N) ? (bn + row) : (N - 1);  // clamp addr
                cp16(stb + (uint32_t)TILE_A_BYTES + (uint32_t)((row * ST + kc * 8) * 2),
                     W + (size_t)wr * K + k0 + kc * 8, ok);
            }
        }
    };

    load_stage(0); cp_commit();
    load_stage(1); cp_commit();

    for (int s = 0; s < nst; s++) {
        cp_wait1();
        __syncthreads();
        load_stage(s + 2);                 // issue next copy before compute
        cp_commit();
        const uint32_t stb = sb + (uint32_t)(s % 3) * STAGE_BYTES;

        #pragma unroll
        for (int ks = 0; ks < 2; ks++) {
            const uint32_t ko = (uint32_t)(ks * 32);  // +16 halves
            uint32_t a[4][4], b[4][4];
            #pragma unroll
            for (int im = 0; im < 4; im++)
                ldsm_x4(stb + aoff + (uint32_t)(im * 16 * ST * 2) + ko,
                        a[im][0], a[im][1], a[im][2], a[im][3]);
            #pragma unroll
            for (int p = 0; p < 4; p++)
                ldsm_x4(stb + boff + (uint32_t)(p * 16 * ST * 2) + ko,
                        b[p][0], b[p][1], b[p][2], b[p][3]);
            #pragma unroll
            for (int im = 0; im < 4; im++)
                #pragma unroll
                for (int jn = 0; jn < 8; jn++)
                    mma_f16(acc[im][jn], a[im],
                            b[jn >> 1][(jn & 1) * 2], b[jn >> 1][(jn & 1) * 2 + 1]);
        }
    }

    // -------- epilogue --------
    #pragma unroll
    for (int im = 0; im < 4; im++) {
        const int r0 = bm + wm * 64 + im * 16 + (lane >> 2);
        const int r1 = r0 + 8;
        #pragma unroll
        for (int jn = 0; jn < 8; jn++) {
            const int c = bn + wn * 64 + jn * 8 + (lane & 3) * 2;
            if (c < N) {
                const float2 bb = *(const float2*)&bias[c];
                float v00 = acc[im][jn][0] + bb.x;
                float v01 = acc[im][jn][1] + bb.y;
                float v10 = acc[im][jn][2] + bb.x;
                float v11 = acc[im][jn][3] + bb.y;
                const size_t i0 = (size_t)r0 * N + c;
                const size_t i1 = (size_t)r1 * N + c;
                if (MODE == 0) {
                    float* C = (float*)Cv;
                    *(float2*)&C[i0] = make_float2(v00, v01);
                    *(float2*)&C[i1] = make_float2(v10, v11);
                    if (C2) {
                        *(float2*)&C2[i0] = make_float2(v00, v01);
                        *(float2*)&C2[i1] = make_float2(v10, v11);
                    }
                } else if (MODE == 1) {
                    __half* C = (__half*)Cv;
                    *(__half2*)&C[i0] = __floats2half2_rn(tanhf(v00), tanhf(v01));
                    *(__half2*)&C[i1] = __floats2half2_rn(tanhf(v10), tanhf(v11));
                } else {
                    float* C = (float*)Cv;
                    const float2 h0 = *(const float2*)&Hold[i0];
                    const float2 h1 = *(const float2*)&Hold[i1];
                    const float2 x0 = *(const float2*)&Xemb[i0];
                    const float2 x1 = *(const float2*)&Xemb[i1];
                    *(float2*)&C[i0] = make_float2(0.5f * h0.x + 0.5f * (v00 + x0.x),
                                                   0.5f * h0.y + 0.5f * (v01 + x0.y));
                    *(float2*)&C[i1] = make_float2(0.5f * h1.x + 0.5f * (v10 + x1.x),
                                                   0.5f * h1.y + 0.5f * (v11 + x1.y));
                }
            }
        }
    }
}

// ---------------------------------------------------------------------------
// fp32 -> fp16 convert with K-padding: in[rows,Kin] -> out[rows,Kout]
// Kin%4==0, Kout%4==0; cols >= Kin are zero.
// ---------------------------------------------------------------------------
__global__ __launch_bounds__(256)
void cvt_pad_kernel(const float* __restrict__ in, __half* __restrict__ out,
                    int Kin, int Kout, int total_out)
{
    const int e = (blockIdx.x * 256 + threadIdx.x) * 4;
    if (e >= total_out) return;
    const int row = e / Kout, col = e % Kout;
    __half2 lo = __floats2half2_rn(0.f, 0.f), hi = lo;
    if (col < Kin) {
        const float4 v = *(const float4*)(in + (size_t)row * Kin + col);
        lo = __floats2half2_rn(v.x, v.y);
        hi = __floats2half2_rn(v.z, v.w);
    }
    __half2* o = (__half2*)(out + (size_t)row * Kout + col);
    o[0] = lo; o[1] = hi;
}

// ---------------------------------------------------------------------------
// LayerNorm over rows of [B_ROWS, 1024]; fp32 in, fp16 out.
// ---------------------------------------------------------------------------
__global__ __launch_bounds__(256)
void layernorm_kernel(const float* __restrict__ Hin,
                      const float* __restrict__ w,
                      const float* __restrict__ b,
                      __half* __restrict__ Out)
{
    __shared__ float ssum[8], ssq[8];
    const int row = blockIdx.x;
    const int tid = threadIdx.x;

    const float4 v = ((const float4*)(Hin + (size_t)row * H_DIM))[tid];
    float s = v.x + v.y + v.z + v.w;
    float q = v.x * v.x + v.y * v.y + v.z * v.z + v.w * v.w;
    #pragma unroll
    for (int o = 16; o > 0; o >>= 1) {
        s += __shfl_xor_sync(0xFFFFFFFFu, s, o);
        q += __shfl_xor_sync(0xFFFFFFFFu, q, o);
    }
    const int warp = tid >> 5, lane = tid & 31;
    if (lane == 0) { ssum[warp] = s; ssq[warp] = q; }
    __syncthreads();
    float ts = 0.f, tq = 0.f;
    #pragma unroll
    for (int i = 0; i < 8; i++) { ts += ssum[i]; tq += ssq[i]; }

    const float mu  = ts * (1.0f / H_DIM);
    const float var = tq * (1.0f / H_DIM) - mu * mu;
    const float inv = rsqrtf(var + LN_EPS);

    const float4 wv = ((const float4*)w)[tid];
    const float4 bv = ((const float4*)b)[tid];
    __half2 lo = __floats2half2_rn((v.x - mu) * inv * wv.x + bv.x,
                                   (v.y - mu) * inv * wv.y + bv.y);
    __half2 hi = __floats2half2_rn((v.z - mu) * inv * wv.z + bv.z,
                                   (v.w - mu) * inv * wv.w + bv.w);
    __half2* o = (__half2*)(Out + (size_t)row * H_DIM + tid * 4);
    o[0] = lo; o[1] = hi;
}

// ---------------------------------------------------------------------------
extern "C" void kernel_launch(void* const* d_in, const int* in_sizes, int n_in,
                              void* d_out, int out_size)
{
    const float* x       = (const float*)d_in[0];
    const float* embed_w = (const float*)d_in[1];
    const float* embed_b = (const float*)d_in[2];
    const float* W1_w    = (const float*)d_in[3];
    const float* W1_b    = (const float*)d_in[4];
    const float* W2_w    = (const float*)d_in[5];
    const float* W2_b    = (const float*)d_in[6];
    const float* norm_w  = (const float*)d_in[7];
    const float* norm_b  = (const float*)d_in[8];
    const float* head_w  = (const float*)d_in[9];
    const float* head_b  = (const float*)d_in[10];
    float* out = (float*)d_out;                     // [4096, 1000]

    float  *ph, *pxe;
    __half *phn, *pffn, *pw1, *pw2, *pxh, *pewh, *phwh;
    cudaGetSymbolAddress((void**)&ph,   g_h);
    cudaGetSymbolAddress((void**)&pxe,  g_xemb);
    cudaGetSymbolAddress((void**)&phn,  g_hn);
    cudaGetSymbolAddress((void**)&pffn, g_ffn);
    cudaGetSymbolAddress((void**)&pw1,  g_w1h);
    cudaGetSymbolAddress((void**)&pw2,  g_w2h);
    cudaGetSymbolAddress((void**)&pxh,  g_xh);
    cudaGetSymbolAddress((void**)&pewh, g_ewh);
    cudaGetSymbolAddress((void**)&phwh, g_hwh);

    cudaFuncSetAttribute(f16_gemm<0>, cudaFuncAttributeMaxDynamicSharedMemorySize, SMEM_BYTES);
    cudaFuncSetAttribute(f16_gemm<1>, cudaFuncAttributeMaxDynamicSharedMemorySize, SMEM_BYTES);
    cudaFuncSetAttribute(f16_gemm<2>, cudaFuncAttributeMaxDynamicSharedMemorySize, SMEM_BYTES);

    dim3 blk(256);
    auto rgrid = [](int total) { return dim3((total / 4 + 255) / 256); };

    // one-shot fp16 conversions (idempotent; part of graph)
    cvt_pad_kernel<<<rgrid(B_ROWS * K_EMB), blk>>>(x, pxh, D_IN, K_EMB, B_ROWS * K_EMB);
    cvt_pad_kernel<<<rgrid(H_DIM * K_EMB), blk>>>(embed_w, pewh, D_IN, K_EMB, H_DIM * K_EMB);
    cvt_pad_kernel<<<rgrid(FFN_DIM * H_DIM), blk>>>(W1_w, pw1, H_DIM, H_DIM, FFN_DIM * H_DIM);
    cvt_pad_kernel<<<rgrid(H_DIM * FFN_DIM), blk>>>(W2_w, pw2, FFN_DIM, FFN_DIM, H_DIM * FFN_DIM);
    cvt_pad_kernel<<<rgrid(D_OUT * H_DIM), blk>>>(head_w, phwh, H_DIM, H_DIM, D_OUT * H_DIM);

    // embed: xemb = xh @ ewh^T + embed_b ; h = xemb
    {
        dim3 grid(H_DIM / 256, B_ROWS / 128);  // (4, 32)
        f16_gemm<0><<<grid, blk, SMEM_BYTES>>>(pxh, pewh, embed_b, pxe, ph,
                                               nullptr, nullptr, B_ROWS, H_DIM, K_EMB);
    }

    for (int s = 0; s < N_STEPS; s++) {
        layernorm_kernel<<<B_ROWS, blk>>>(ph, norm_w, norm_b, phn);
        // ffn = tanh(hn @ W1^T + b1)  -> fp16
        {
            dim3 grid(FFN_DIM / 256, B_ROWS / 128);  // (16, 32)
            f16_gemm<1><<<grid, blk, SMEM_BYTES>>>(phn, pw1, W1_b, pffn, nullptr,
                                                   nullptr, nullptr, B_ROWS, FFN_DIM, H_DIM);
        }
        // h = 0.5h + 0.5(ffn @ W2^T + b2 + xemb)
        {
            dim3 grid(H_DIM / 256, B_ROWS / 128);    // (4, 32)
            f16_gemm<2><<<grid, blk, SMEM_BYTES>>>(pffn, pw2, W2_b, ph, nullptr,
                                                   ph, pxe, B_ROWS, H_DIM, FFN_DIM);
        }
    }

    // head: out = half(h) @ hwh^T + head_b
    cvt_pad_kernel<<<rgrid(B_ROWS * H_DIM), blk>>>(ph, phn, H_DIM, H_DIM, B_ROWS * H_DIM);
    {
        dim3 grid((D_OUT + 255) / 256, B_ROWS / 128);  // (4, 32)
        f16_gemm<0><<<grid, blk, SMEM_BYTES>>>(phn, phwh, head_b, out, nullptr,
                                               nullptr, nullptr, B_ROWS, D_OUT, H_DIM);
    }
}

// round 12
// speedup vs baseline: 1.2215x; 1.2215x over previous
#include <cuda_runtime.h>
#include <cuda_fp16.h>
#include <math.h>
#include <stdint.h>

#define H_DIM 1024
#define FFN_DIM 4096
#define B_ROWS 4096
#define D_IN 784
#define K_EMB 800
#define D_OUT 1000
#define N_STEPS 30
#define LN_EPS 1e-5f

// ---------------- scratch (device globals; no allocation allowed) ----------
__device__ float  g_h[(size_t)B_ROWS * H_DIM];        // 16 MB fp32 state
__device__ float  g_xemb[(size_t)B_ROWS * H_DIM];     // 16 MB fp32
__device__ __half g_hn[(size_t)B_ROWS * H_DIM];       // 8 MB  (LN out / head A)
__device__ __half g_ffn[(size_t)B_ROWS * FFN_DIM];    // 32 MB (tanh out)
__device__ __half g_w1h[(size_t)FFN_DIM * H_DIM];     // 8 MB
__device__ __half g_w2h[(size_t)H_DIM * FFN_DIM];     // 8 MB
__device__ __half g_xh [(size_t)B_ROWS * K_EMB];      // 6.5 MB (x padded)
__device__ __half g_ewh[(size_t)H_DIM * K_EMB];       // 1.6 MB (embed_w padded)
__device__ __half g_hwh[(size_t)D_OUT * H_DIM];       // 2 MB   (head_w)

// ---------------- PTX helpers ----------------------------------------------
__device__ __forceinline__ uint32_t smem_u32(const void* p) {
    return (uint32_t)__cvta_generic_to_shared(p);
}
__device__ __forceinline__ void cp16(uint32_t dst, const void* src, int sz) {
    asm volatile("cp.async.cg.shared.global [%0], [%1], 16, %2;"
                 :: "r"(dst), "l"(src), "r"(sz));
}
__device__ __forceinline__ void cp_commit() { asm volatile("cp.async.commit_group;"); }
__device__ __forceinline__ void cp_wait1() {
    asm volatile("cp.async.wait_group 1;" ::: "memory");
}
__device__ __forceinline__ void ldsm_x4(uint32_t addr, uint32_t& r0, uint32_t& r1,
                                        uint32_t& r2, uint32_t& r3) {
    asm volatile("ldmatrix.sync.aligned.m8n8.x4.shared.b16 {%0,%1,%2,%3}, [%4];"
                 : "=r"(r0), "=r"(r1), "=r"(r2), "=r"(r3) : "r"(addr));
}
__device__ __forceinline__ void mma_f16(float* d, const uint32_t* a, uint32_t b0, uint32_t b1) {
    asm volatile("mma.sync.aligned.m16n8k16.row.col.f32.f16.f16.f32 "
                 "{%0,%1,%2,%3}, {%4,%5,%6,%7}, {%8,%9}, {%0,%1,%2,%3};"
                 : "+f"(d[0]), "+f"(d[1]), "+f"(d[2]), "+f"(d[3])
                 : "r"(a[0]), "r"(a[1]), "r"(a[2]), "r"(a[3]), "r"(b0), "r"(b1));
}

// ---------------------------------------------------------------------------
// FP16 tensor GEMM: C[M,N] = epi( A[M,K] @ W[N,K]^T + bias[N] )
// 128x128 CTA tile, BK=32, 3-stage cp.async ring, 256 threads (8 warps 2x4),
// warp tile 64x32, m16n8k16 f16 mma, fp32 accumulators, 2 CTAs/SM.
// M%128==0, K%32==0; N guarded (zfill w/ clamped src + epilogue guard).
// MODE 0: C(fp32)=v, C2(fp32)=v if set
// MODE 1: C(fp16)=half(tanh(v))
// MODE 2: C(fp32)=0.5*Hold + 0.5*(v + Xemb)
// ---------------------------------------------------------------------------
#define ST 40                           // smem row stride in halves
#define TILE_BYTES (128 * ST * 2)       // 10240
#define STAGE_BYTES (2 * TILE_BYTES)    // 20480
#define SMEM_BYTES (3 * STAGE_BYTES)    // 61440  (x2 CTAs = 123 KB/SM)

template <int MODE>
__global__ __launch_bounds__(256, 2)
void f16_gemm(const __half* __restrict__ A, const __half* __restrict__ W,
              const float* __restrict__ bias, void* __restrict__ Cv,
              float* __restrict__ C2, const float* __restrict__ Hold,
              const float* __restrict__ Xemb, int M, int N, int K)
{
    extern __shared__ char smem[];
    const uint32_t sb = smem_u32(smem);
    const int tid  = threadIdx.x;
    const int lane = tid & 31;
    const int warp = tid >> 5;
    const int wm = warp >> 2;           // 0..1
    const int wn = warp & 3;            // 0..3
    const int bm = blockIdx.y * 128;
    const int bn = blockIdx.x * 128;
    const int nst = K >> 5;

    // ldmatrix per-thread byte offsets within a stage
    const int grp = lane >> 3, r8 = lane & 7;
    const uint32_t aoff = (uint32_t)(((wm * 64 + (lane & 15)) * ST + (lane >> 4) * 8) * 2);
    const uint32_t boff = (uint32_t)TILE_BYTES +
        (uint32_t)(((wn * 32 + (grp >> 1) * 8 + r8) * ST + (grp & 1) * 8) * 2);

    float acc[4][4][4];
    #pragma unroll
    for (int i = 0; i < 4; i++)
        #pragma unroll
        for (int j = 0; j < 4; j++)
            #pragma unroll
            for (int r = 0; r < 4; r++) acc[i][j][r] = 0.0f;

    auto load_stage = [&](int s) {
        if (s >= nst) return;
        const uint32_t stb = sb + (uint32_t)(s % 3) * STAGE_BYTES;
        const int k0 = s << 5;
        #pragma unroll
        for (int i = 0; i < 4; i++) {
            const int c = tid + (i << 8);   // 0..1023
            if (c < 512) {                  // A: 128 rows x 4 x 16B
                const int row = c >> 2, kc = c & 3;
                cp16(stb + (uint32_t)((row * ST + kc * 8) * 2),
                     A + (size_t)(bm + row) * K + k0 + kc * 8, 16);
            } else {                        // W: 128 rows x 4 x 16B (zfill > N)
                const int c2 = c - 512;
                const int row = c2 >> 2, kc = c2 & 3;
                const int ok = ((bn + row) < N) ? 16 : 0;
                const int wr = ((bn + row) < N) ? (bn + row) : (N - 1);  // clamp addr
                cp16(stb + (uint32_t)TILE_BYTES + (uint32_t)((row * ST + kc * 8) * 2),
                     W + (size_t)wr * K + k0 + kc * 8, ok);
            }
        }
    };

    load_stage(0); cp_commit();
    load_stage(1); cp_commit();

    for (int s = 0; s < nst; s++) {
        cp_wait1();
        __syncthreads();
        load_stage(s + 2);              // issue next copy before compute
        cp_commit();
        const uint32_t stb = sb + (uint32_t)(s % 3) * STAGE_BYTES;

        #pragma unroll
        for (int ks = 0; ks < 2; ks++) {
            const uint32_t ko = (uint32_t)(ks * 32);  // +16 halves
            uint32_t a[4][4], b[2][4];
            #pragma unroll
            for (int im = 0; im < 4; im++)
                ldsm_x4(stb + aoff + (uint32_t)(im * 16 * ST * 2) + ko,
                        a[im][0], a[im][1], a[im][2], a[im][3]);
            #pragma unroll
            for (int p = 0; p < 2; p++)
                ldsm_x4(stb + boff + (uint32_t)(p * 16 * ST * 2) + ko,
                        b[p][0], b[p][1], b[p][2], b[p][3]);
            #pragma unroll
            for (int im = 0; im < 4; im++)
                #pragma unroll
                for (int jn = 0; jn < 4; jn++)
                    mma_f16(acc[im][jn], a[im],
                            b[jn >> 1][(jn & 1) * 2], b[jn >> 1][(jn & 1) * 2 + 1]);
        }
    }

    // -------- epilogue --------
    #pragma unroll
    for (int im = 0; im < 4; im++) {
        const int r0 = bm + wm * 64 + im * 16 + (lane >> 2);
        const int r1 = r0 + 8;
        #pragma unroll
        for (int jn = 0; jn < 4; jn++) {
            const int c = bn + wn * 32 + jn * 8 + (lane & 3) * 2;
            if (c < N) {
                const float2 bb = *(const float2*)&bias[c];
                float v00 = acc[im][jn][0] + bb.x;
                float v01 = acc[im][jn][1] + bb.y;
                float v10 = acc[im][jn][2] + bb.x;
                float v11 = acc[im][jn][3] + bb.y;
                const size_t i0 = (size_t)r0 * N + c;
                const size_t i1 = (size_t)r1 * N + c;
                if (MODE == 0) {
                    float* C = (float*)Cv;
                    *(float2*)&C[i0] = make_float2(v00, v01);
                    *(float2*)&C[i1] = make_float2(v10, v11);
                    if (C2) {
                        *(float2*)&C2[i0] = make_float2(v00, v01);
                        *(float2*)&C2[i1] = make_float2(v10, v11);
                    }
                } else if (MODE == 1) {
                    __half* C = (__half*)Cv;
                    *(__half2*)&C[i0] = __floats2half2_rn(tanhf(v00), tanhf(v01));
                    *(__half2*)&C[i1] = __floats2half2_rn(tanhf(v10), tanhf(v11));
                } else {
                    float* C = (float*)Cv;
                    const float2 h0 = *(const float2*)&Hold[i0];
                    const float2 h1 = *(const float2*)&Hold[i1];
                    const float2 x0 = *(const float2*)&Xemb[i0];
                    const float2 x1 = *(const float2*)&Xemb[i1];
                    *(float2*)&C[i0] = make_float2(0.5f * h0.x + 0.5f * (v00 + x0.x),
                                                   0.5f * h0.y + 0.5f * (v01 + x0.y));
                    *(float2*)&C[i1] = make_float2(0.5f * h1.x + 0.5f * (v10 + x1.x),
                                                   0.5f * h1.y + 0.5f * (v11 + x1.y));
                }
            }
        }
    }
}

// ---------------------------------------------------------------------------
// fp32 -> fp16 convert with K-padding: in[rows,Kin] -> out[rows,Kout]
// Kin%4==0, Kout%4==0; cols >= Kin are zero.
// ---------------------------------------------------------------------------
__global__ __launch_bounds__(256)
void cvt_pad_kernel(const float* __restrict__ in, __half* __restrict__ out,
                    int Kin, int Kout, int total_out)
{
    const int e = (blockIdx.x * 256 + threadIdx.x) * 4;
    if (e >= total_out) return;
    const int row = e / Kout, col = e % Kout;
    __half2 lo = __floats2half2_rn(0.f, 0.f), hi = lo;
    if (col < Kin) {
        const float4 v = *(const float4*)(in + (size_t)row * Kin + col);
        lo = __floats2half2_rn(v.x, v.y);
        hi = __floats2half2_rn(v.z, v.w);
    }
    __half2* o = (__half2*)(out + (size_t)row * Kout + col);
    o[0] = lo; o[1] = hi;
}

// ---------------------------------------------------------------------------
// LayerNorm over rows of [B_ROWS, 1024]; fp32 in, fp16 out.
// ---------------------------------------------------------------------------
__global__ __launch_bounds__(256)
void layernorm_kernel(const float* __restrict__ Hin,
                      const float* __restrict__ w,
                      const float* __restrict__ b,
                      __half* __restrict__ Out)
{
    __shared__ float ssum[8], ssq[8];
    const int row = blockIdx.x;
    const int tid = threadIdx.x;

    const float4 v = ((const float4*)(Hin + (size_t)row * H_DIM))[tid];
    float s = v.x + v.y + v.z + v.w;
    float q = v.x * v.x + v.y * v.y + v.z * v.z + v.w * v.w;
    #pragma unroll
    for (int o = 16; o > 0; o >>= 1) {
        s += __shfl_xor_sync(0xFFFFFFFFu, s, o);
        q += __shfl_xor_sync(0xFFFFFFFFu, q, o);
    }
    const int warp = tid >> 5, lane = tid & 31;
    if (lane == 0) { ssum[warp] = s; ssq[warp] = q; }
    __syncthreads();
    float ts = 0.f, tq = 0.f;
    #pragma unroll
    for (int i = 0; i < 8; i++) { ts += ssum[i]; tq += ssq[i]; }

    const float mu  = ts * (1.0f / H_DIM);
    const float var = tq * (1.0f / H_DIM) - mu * mu;
    const float inv = rsqrtf(var + LN_EPS);

    const float4 wv = ((const float4*)w)[tid];
    const float4 bv = ((const float4*)b)[tid];
    __half2 lo = __floats2half2_rn((v.x - mu) * inv * wv.x + bv.x,
                                   (v.y - mu) * inv * wv.y + bv.y);
    __half2 hi = __floats2half2_rn((v.z - mu) * inv * wv.z + bv.z,
                                   (v.w - mu) * inv * wv.w + bv.w);
    __half2* o = (__half2*)(Out + (size_t)row * H_DIM + tid * 4);
    o[0] = lo; o[1] = hi;
}

// ---------------------------------------------------------------------------
extern "C" void kernel_launch(void* const* d_in, const int* in_sizes, int n_in,
                              void* d_out, int out_size)
{
    const float* x       = (const float*)d_in[0];
    const float* embed_w = (const float*)d_in[1];
    const float* embed_b = (const float*)d_in[2];
    const float* W1_w    = (const float*)d_in[3];
    const float* W1_b    = (const float*)d_in[4];
    const float* W2_w    = (const float*)d_in[5];
    const float* W2_b    = (const float*)d_in[6];
    const float* norm_w  = (const float*)d_in[7];
    const float* norm_b  = (const float*)d_in[8];
    const float* head_w  = (const float*)d_in[9];
    const float* head_b  = (const float*)d_in[10];
    float* out = (float*)d_out;                     // [4096, 1000]

    float  *ph, *pxe;
    __half *phn, *pffn, *pw1, *pw2, *pxh, *pewh, *phwh;
    cudaGetSymbolAddress((void**)&ph,   g_h);
    cudaGetSymbolAddress((void**)&pxe,  g_xemb);
    cudaGetSymbolAddress((void**)&phn,  g_hn);
    cudaGetSymbolAddress((void**)&pffn, g_ffn);
    cudaGetSymbolAddress((void**)&pw1,  g_w1h);
    cudaGetSymbolAddress((void**)&pw2,  g_w2h);
    cudaGetSymbolAddress((void**)&pxh,  g_xh);
    cudaGetSymbolAddress((void**)&pewh, g_ewh);
    cudaGetSymbolAddress((void**)&phwh, g_hwh);

    cudaFuncSetAttribute(f16_gemm<0>, cudaFuncAttributeMaxDynamicSharedMemorySize, SMEM_BYTES);
    cudaFuncSetAttribute(f16_gemm<1>, cudaFuncAttributeMaxDynamicSharedMemorySize, SMEM_BYTES);
    cudaFuncSetAttribute(f16_gemm<2>, cudaFuncAttributeMaxDynamicSharedMemorySize, SMEM_BYTES);

    dim3 blk(256);
    auto rgrid = [](int total) { return dim3((total / 4 + 255) / 256); };

    // one-shot fp16 conversions (idempotent; part of graph)
    cvt_pad_kernel<<<rgrid(B_ROWS * K_EMB), blk>>>(x, pxh, D_IN, K_EMB, B_ROWS * K_EMB);
    cvt_pad_kernel<<<rgrid(H_DIM * K_EMB), blk>>>(embed_w, pewh, D_IN, K_EMB, H_DIM * K_EMB);
    cvt_pad_kernel<<<rgrid(FFN_DIM * H_DIM), blk>>>(W1_w, pw1, H_DIM, H_DIM, FFN_DIM * H_DIM);
    cvt_pad_kernel<<<rgrid(H_DIM * FFN_DIM), blk>>>(W2_w, pw2, FFN_DIM, FFN_DIM, H_DIM * FFN_DIM);
    cvt_pad_kernel<<<rgrid(D_OUT * H_DIM), blk>>>(head_w, phwh, H_DIM, H_DIM, D_OUT * H_DIM);

    // embed: xemb = xh @ ewh^T + embed_b ; h = xemb
    {
        dim3 grid(H_DIM / 128, B_ROWS / 128);  // (8, 32)
        f16_gemm<0><<<grid, blk, SMEM_BYTES>>>(pxh, pewh, embed_b, pxe, ph,
                                               nullptr, nullptr, B_ROWS, H_DIM, K_EMB);
    }

    for (int s = 0; s < N_STEPS; s++) {
        layernorm_kernel<<<B_ROWS, blk>>>(ph, norm_w, norm_b, phn);
        // ffn = tanh(hn @ W1^T + b1)  -> fp16
        {
            dim3 grid(FFN_DIM / 128, B_ROWS / 128);  // (32, 32)
            f16_gemm<1><<<grid, blk, SMEM_BYTES>>>(phn, pw1, W1_b, pffn, nullptr,
                                                   nullptr, nullptr, B_ROWS, FFN_DIM, H_DIM);
        }
        // h = 0.5h + 0.5(ffn @ W2^T + b2 + xemb)
        {
            dim3 grid(H_DIM / 128, B_ROWS / 128);    // (8, 32)
            f16_gemm<2><<<grid, blk, SMEM_BYTES>>>(pffn, pw2, W2_b, ph, nullptr,
                                                   ph, pxe, B_ROWS, H_DIM, FFN_DIM);
        }
    }

    // head: out = half(h) @ hwh^T + head_b
    cvt_pad_kernel<<<rgrid(B_ROWS * H_DIM), blk>>>(ph, phn, H_DIM, H_DIM, B_ROWS * H_DIM);
    {
        dim3 grid((D_OUT + 127) / 128, B_ROWS / 128);  // (8, 32)
        f16_gemm<0><<<grid, blk, SMEM_BYTES>>>(phn, phwh, head_b, out, nullptr,
                                               nullptr, nullptr, B_ROWS, D_OUT, H_DIM);
    }
}

// round 14
// speedup vs baseline: 1.3331x; 1.0914x over previous
#include <cuda_runtime.h>
#include <cuda_fp16.h>
#include <math.h>
#include <stdint.h>

#define H_DIM 1024
#define FFN_DIM 4096
#define B_ROWS 4096
#define D_IN 784
#define K_EMB 832
#define D_OUT 1000
#define N_STEPS 30
#define LN_EPS 1e-5f

// ---------------- scratch (device globals; no allocation allowed) ----------
__device__ float  g_h[(size_t)B_ROWS * H_DIM];        // 16 MB fp32 state
__device__ float  g_xemb[(size_t)B_ROWS * H_DIM];     // 16 MB fp32
__device__ __half g_hn[(size_t)B_ROWS * H_DIM];       // 8 MB  (LN out / head A)
__device__ __half g_ffn[(size_t)B_ROWS * FFN_DIM];    // 32 MB (tanh out)
__device__ __half g_w1h[(size_t)FFN_DIM * H_DIM];     // 8 MB
__device__ __half g_w2h[(size_t)H_DIM * FFN_DIM];     // 8 MB
__device__ __half g_xh [(size_t)B_ROWS * K_EMB];      // 6.8 MB (x padded to 832)
__device__ __half g_ewh[(size_t)H_DIM * K_EMB];       // 1.7 MB (embed_w padded)
__device__ __half g_hwh[(size_t)D_OUT * H_DIM];       // 2 MB   (head_w)

// ---------------- PTX helpers ----------------------------------------------
__device__ __forceinline__ uint32_t smem_u32(const void* p) {
    return (uint32_t)__cvta_generic_to_shared(p);
}
__device__ __forceinline__ void cp16(uint32_t dst, const void* src, int sz) {
    asm volatile("cp.async.cg.shared.global [%0], [%1], 16, %2;"
                 :: "r"(dst), "l"(src), "r"(sz));
}
__device__ __forceinline__ void cp_commit() { asm volatile("cp.async.commit_group;"); }
__device__ __forceinline__ void cp_wait0() {
    asm volatile("cp.async.wait_group 0;" ::: "memory");
}
__device__ __forceinline__ void ldsm_x4(uint32_t addr, uint32_t& r0, uint32_t& r1,
                                        uint32_t& r2, uint32_t& r3) {
    asm volatile("ldmatrix.sync.aligned.m8n8.x4.shared.b16 {%0,%1,%2,%3}, [%4];"
                 : "=r"(r0), "=r"(r1), "=r"(r2), "=r"(r3) : "r"(addr));
}
__device__ __forceinline__ void mma_f16(float* d, const uint32_t* a, uint32_t b0, uint32_t b1) {
    asm volatile("mma.sync.aligned.m16n8k16.row.col.f32.f16.f16.f32 "
                 "{%0,%1,%2,%3}, {%4,%5,%6,%7}, {%8,%9}, {%0,%1,%2,%3};"
                 : "+f"(d[0]), "+f"(d[1]), "+f"(d[2]), "+f"(d[3])
                 : "r"(a[0]), "r"(a[1]), "r"(a[2]), "r"(a[3]), "r"(b0), "r"(b1));
}

// ---------------------------------------------------------------------------
// FP16 tensor GEMM: C[M,N] = epi( A[M,K] @ W[N,K]^T + bias[N] )
// 128x128 CTA tile, BK=64, 2-stage cp.async double buffer, 256 threads
// (8 warps 2x4), warp tile 64x32, m16n8k16 f16 mma, fp32 acc, 2 CTAs/SM.
// M%128==0, K%64==0; N guarded (zfill w/ clamped src + epilogue guard).
// MODE 0: C(fp32)=v, C2(fp32)=v if set
// MODE 1: C(fp16)=half(tanh(v))
// MODE 2: C(fp32)=0.5*Hold + 0.5*(v + Xemb)
// (Resubmission of R12 — infra failure gave no measurement.)
// ---------------------------------------------------------------------------
#define ST 72                           // smem row stride in halves (64 + 8 pad)
#define TILE_BYTES (128 * ST * 2)       // 18432
#define STAGE_BYTES (2 * TILE_BYTES)    // 36864
#define SMEM_BYTES (2 * STAGE_BYTES)    // 73728  (x2 CTAs = 147 KB/SM)

template <int MODE>
__global__ __launch_bounds__(256, 2)
void f16_gemm(const __half* __restrict__ A, const __half* __restrict__ W,
              const float* __restrict__ bias, void* __restrict__ Cv,
              float* __restrict__ C2, const float* __restrict__ Hold,
              const float* __restrict__ Xemb, int M, int N, int K)
{
    extern __shared__ char smem[];
    const uint32_t sb = smem_u32(smem);
    const int tid  = threadIdx.x;
    const int lane = tid & 31;
    const int warp = tid >> 5;
    const int wm = warp >> 2;           // 0..1
    const int wn = warp & 3;            // 0..3
    const int bm = blockIdx.y * 128;
    const int bn = blockIdx.x * 128;
    const int nst = K >> 6;

    // ldmatrix per-thread byte offsets within a stage
    const int grp = lane >> 3, r8 = lane & 7;
    const uint32_t aoff = (uint32_t)(((wm * 64 + (lane & 15)) * ST + (lane >> 4) * 8) * 2);
    const uint32_t boff = (uint32_t)TILE_BYTES +
        (uint32_t)(((wn * 32 + (grp >> 1) * 8 + r8) * ST + (grp & 1) * 8) * 2);

    float acc[4][4][4];
    #pragma unroll
    for (int i = 0; i < 4; i++)
        #pragma unroll
        for (int j = 0; j < 4; j++)
            #pragma unroll
            for (int r = 0; r < 4; r++) acc[i][j][r] = 0.0f;

    auto load_stage = [&](int s) {
        if (s >= nst) return;
        const uint32_t stb = sb + (uint32_t)(s & 1) * STAGE_BYTES;
        const int k0 = s << 6;
        #pragma unroll
        for (int i = 0; i < 8; i++) {
            const int c = tid + (i << 8);   // 0..2047
            if (c < 1024) {                 // A: 128 rows x 8 x 16B
                const int row = c >> 3, kc = c & 7;
                cp16(stb + (uint32_t)((row * ST + kc * 8) * 2),
                     A + (size_t)(bm + row) * K + k0 + kc * 8, 16);
            } else {                        // W: 128 rows x 8 x 16B (zfill > N)
                const int c2 = c - 1024;
                const int row = c2 >> 3, kc = c2 & 7;
                const int ok = ((bn + row) < N) ? 16 : 0;
                const int wr = ((bn + row) < N) ? (bn + row) : (N - 1);  // clamp addr
                cp16(stb + (uint32_t)TILE_BYTES + (uint32_t)((row * ST + kc * 8) * 2),
                     W + (size_t)wr * K + k0 + kc * 8, ok);
            }
        }
    };

    load_stage(0); cp_commit();

    for (int s = 0; s < nst; s++) {
        cp_wait0();                     // stage s resident
        __syncthreads();                // everyone done with buffer (s+1)&1
        load_stage(s + 1);              // overlaps compute of stage s
        cp_commit();
        const uint32_t stb = sb + (uint32_t)(s & 1) * STAGE_BYTES;

        #pragma unroll
        for (int ks = 0; ks < 4; ks++) {
            const uint32_t ko = (uint32_t)(ks * 32);  // +16 halves per ks
            uint32_t a[4][4], b[2][4];
            #pragma unroll
            for (int im = 0; im < 4; im++)
                ldsm_x4(stb + aoff + (uint32_t)(im * 16 * ST * 2) + ko,
                        a[im][0], a[im][1], a[im][2], a[im][3]);
            #pragma unroll
            for (int p = 0; p < 2; p++)
                ldsm_x4(stb + boff + (uint32_t)(p * 16 * ST * 2) + ko,
                        b[p][0], b[p][1], b[p][2], b[p][3]);
            #pragma unroll
            for (int im = 0; im < 4; im++)
                #pragma unroll
                for (int jn = 0; jn < 4; jn++)
                    mma_f16(acc[im][jn], a[im],
                            b[jn >> 1][(jn & 1) * 2], b[jn >> 1][(jn & 1) * 2 + 1]);
        }
    }

    // -------- epilogue --------
    #pragma unroll
    for (int im = 0; im < 4; im++) {
        const int r0 = bm + wm * 64 + im * 16 + (lane >> 2);
        const int r1 = r0 + 8;
        #pragma unroll
        for (int jn = 0; jn < 4; jn++) {
            const int c = bn + wn * 32 + jn * 8 + (lane & 3) * 2;
            if (c < N) {
                const float2 bb = *(const float2*)&bias[c];
                float v00 = acc[im][jn][0] + bb.x;
                float v01 = acc[im][jn][1] + bb.y;
                float v10 = acc[im][jn][2] + bb.x;
                float v11 = acc[im][jn][3] + bb.y;
                const size_t i0 = (size_t)r0 * N + c;
                const size_t i1 = (size_t)r1 * N + c;
                if (MODE == 0) {
                    float* C = (float*)Cv;
                    *(float2*)&C[i0] = make_float2(v00, v01);
                    *(float2*)&C[i1] = make_float2(v10, v11);
                    if (C2) {
                        *(float2*)&C2[i0] = make_float2(v00, v01);
                        *(float2*)&C2[i1] = make_float2(v10, v11);
                    }
                } else if (MODE == 1) {
                    __half* C = (__half*)Cv;
                    *(__half2*)&C[i0] = __floats2half2_rn(tanhf(v00), tanhf(v01));
                    *(__half2*)&C[i1] = __floats2half2_rn(tanhf(v10), tanhf(v11));
                } else {
                    float* C = (float*)Cv;
                    const float2 h0 = *(const float2*)&Hold[i0];
                    const float2 h1 = *(const float2*)&Hold[i1];
                    const float2 x0 = *(const float2*)&Xemb[i0];
                    const float2 x1 = *(const float2*)&Xemb[i1];
                    *(float2*)&C[i0] = make_float2(0.5f * h0.x + 0.5f * (v00 + x0.x),
                                                   0.5f * h0.y + 0.5f * (v01 + x0.y));
                    *(float2*)&C[i1] = make_float2(0.5f * h1.x + 0.5f * (v10 + x1.x),
                                                   0.5f * h1.y + 0.5f * (v11 + x1.y));
                }
            }
        }
    }
}

// ---------------------------------------------------------------------------
// fp32 -> fp16 convert with K-padding: in[rows,Kin] -> out[rows,Kout]
// Kin%4==0, Kout%4==0; cols >= Kin are zero.
// ---------------------------------------------------------------------------
__global__ __launch_bounds__(256)
void cvt_pad_kernel(const float* __restrict__ in, __half* __restrict__ out,
                    int Kin, int Kout, int total_out)
{
    const int e = (blockIdx.x * 256 + threadIdx.x) * 4;
    if (e >= total_out) return;
    const int row = e / Kout, col = e % Kout;
    __half2 lo = __floats2half2_rn(0.f, 0.f), hi = lo;
    if (col < Kin) {
        const float4 v = *(const float4*)(in + (size_t)row * Kin + col);
        lo = __floats2half2_rn(v.x, v.y);
        hi = __floats2half2_rn(v.z, v.w);
    }
    __half2* o = (__half2*)(out + (size_t)row * Kout + col);
    o[0] = lo; o[1] = hi;
}

// ---------------------------------------------------------------------------
// LayerNorm over rows of [B_ROWS, 1024]; fp32 in, fp16 out.
// ---------------------------------------------------------------------------
__global__ __launch_bounds__(256)
void layernorm_kernel(const float* __restrict__ Hin,
                      const float* __restrict__ w,
                      const float* __restrict__ b,
                      __half* __restrict__ Out)
{
    __shared__ float ssum[8], ssq[8];
    const int row = blockIdx.x;
    const int tid = threadIdx.x;

    const float4 v = ((const float4*)(Hin + (size_t)row * H_DIM))[tid];
    float s = v.x + v.y + v.z + v.w;
    float q = v.x * v.x + v.y * v.y + v.z * v.z + v.w * v.w;
    #pragma unroll
    for (int o = 16; o > 0; o >>= 1) {
        s += __shfl_xor_sync(0xFFFFFFFFu, s, o);
        q += __shfl_xor_sync(0xFFFFFFFFu, q, o);
    }
    const int warp = tid >> 5, lane = tid & 31;
    if (lane == 0) { ssum[warp] = s; ssq[warp] = q; }
    __syncthreads();
    float ts = 0.f, tq = 0.f;
    #pragma unroll
    for (int i = 0; i < 8; i++) { ts += ssum[i]; tq += ssq[i]; }

    const float mu  = ts * (1.0f / H_DIM);
    const float var = tq * (1.0f / H_DIM) - mu * mu;
    const float inv = rsqrtf(var + LN_EPS);

    const float4 wv = ((const float4*)w)[tid];
    const float4 bv = ((const float4*)b)[tid];
    __half2 lo = __floats2half2_rn((v.x - mu) * inv * wv.x + bv.x,
                                   (v.y - mu) * inv * wv.y + bv.y);
    __half2 hi = __floats2half2_rn((v.z - mu) * inv * wv.z + bv.z,
                                   (v.w - mu) * inv * wv.w + bv.w);
    __half2* o = (__half2*)(Out + (size_t)row * H_DIM + tid * 4);
    o[0] = lo; o[1] = hi;
}

// ---------------------------------------------------------------------------
extern "C" void kernel_launch(void* const* d_in, const int* in_sizes, int n_in,
                              void* d_out, int out_size)
{
    const float* x       = (const float*)d_in[0];
    const float* embed_w = (const float*)d_in[1];
    const float* embed_b = (const float*)d_in[2];
    const float* W1_w    = (const float*)d_in[3];
    const float* W1_b    = (const float*)d_in[4];
    const float* W2_w    = (const float*)d_in[5];
    const float* W2_b    = (const float*)d_in[6];
    const float* norm_w  = (const float*)d_in[7];
    const float* norm_b  = (const float*)d_in[8];
    const float* head_w  = (const float*)d_in[9];
    const float* head_b  = (const float*)d_in[10];
    float* out = (float*)d_out;                     // [4096, 1000]

    float  *ph, *pxe;
    __half *phn, *pffn, *pw1, *pw2, *pxh, *pewh, *phwh;
    cudaGetSymbolAddress((void**)&ph,   g_h);
    cudaGetSymbolAddress((void**)&pxe,  g_xemb);
    cudaGetSymbolAddress((void**)&phn,  g_hn);
    cudaGetSymbolAddress((void**)&pffn, g_ffn);
    cudaGetSymbolAddress((void**)&pw1,  g_w1h);
    cudaGetSymbolAddress((void**)&pw2,  g_w2h);
    cudaGetSymbolAddress((void**)&pxh,  g_xh);
    cudaGetSymbolAddress((void**)&pewh, g_ewh);
    cudaGetSymbolAddress((void**)&phwh, g_hwh);

    cudaFuncSetAttribute(f16_gemm<0>, cudaFuncAttributeMaxDynamicSharedMemorySize, SMEM_BYTES);
    cudaFuncSetAttribute(f16_gemm<1>, cudaFuncAttributeMaxDynamicSharedMemorySize, SMEM_BYTES);
    cudaFuncSetAttribute(f16_gemm<2>, cudaFuncAttributeMaxDynamicSharedMemorySize, SMEM_BYTES);

    dim3 blk(256);
    auto rgrid = [](int total) { return dim3((total / 4 + 255) / 256); };

    // one-shot fp16 conversions (idempotent; part of graph)
    cvt_pad_kernel<<<rgrid(B_ROWS * K_EMB), blk>>>(x, pxh, D_IN, K_EMB, B_ROWS * K_EMB);
    cvt_pad_kernel<<<rgrid(H_DIM * K_EMB), blk>>>(embed_w, pewh, D_IN, K_EMB, H_DIM * K_EMB);
    cvt_pad_kernel<<<rgrid(FFN_DIM * H_DIM), blk>>>(W1_w, pw1, H_DIM, H_DIM, FFN_DIM * H_DIM);
    cvt_pad_kernel<<<rgrid(H_DIM * FFN_DIM), blk>>>(W2_w, pw2, FFN_DIM, FFN_DIM, H_DIM * FFN_DIM);
    cvt_pad_kernel<<<rgrid(D_OUT * H_DIM), blk>>>(head_w, phwh, H_DIM, H_DIM, D_OUT * H_DIM);

    // embed: xemb = xh @ ewh^T + embed_b ; h = xemb
    {
        dim3 grid(H_DIM / 128, B_ROWS / 128);  // (8, 32)
        f16_gemm<0><<<grid, blk, SMEM_BYTES>>>(pxh, pewh, embed_b, pxe, ph,
                                               nullptr, nullptr, B_ROWS, H_DIM, K_EMB);
    }

    for (int s = 0; s < N_STEPS; s++) {
        layernorm_kernel<<<B_ROWS, blk>>>(ph, norm_w, norm_b, phn);
        // ffn = tanh(hn @ W1^T + b1)  -> fp16
        {
            dim3 grid(FFN_DIM / 128, B_ROWS / 128);  // (32, 32)
            f16_gemm<1><<<grid, blk, SMEM_BYTES>>>(phn, pw1, W1_b, pffn, nullptr,
                                                   nullptr, nullptr, B_ROWS, FFN_DIM, H_DIM);
        }
        // h = 0.5h + 0.5(ffn @ W2^T + b2 + xemb)
        {
            dim3 grid(H_DIM / 128, B_ROWS / 128);    // (8, 32)
            f16_gemm<2><<<grid, blk, SMEM_BYTES>>>(pffn, pw2, W2_b, ph, nullptr,
                                                   ph, pxe, B_ROWS, H_DIM, FFN_DIM);
        }
    }

    // head: out = half(h) @ hwh^T + head_b
    cvt_pad_kernel<<<rgrid(B_ROWS * H_DIM), blk>>>(ph, phn, H_DIM, H_DIM, B_ROWS * H_DIM);
    {
        dim3 grid((D_OUT + 127) / 128, B_ROWS / 128);  // (8, 32)
        f16_gemm<0><<<grid, blk, SMEM_BYTES>>>(phn, phwh, head_b, out, nullptr,
                                               nullptr, nullptr, B_ROWS, D_OUT, H_DIM);
    }
}